// round 9
// baseline (speedup 1.0000x reference)
#include <cuda_runtime.h>
#include <math.h>

#define T_DIM 2048
#define C_DIM 8
#define S_DIM 16
#define N_DIM 10000
#define NT 32
#define TT 64

// ---------------- scratch ----------------
__device__ float g_E[C_DIM * S_DIM * N_DIM];        // emission probs [c][s][n]
__device__ float g_H[T_DIM * C_DIM * S_DIM];        // hidden probs [t][c][s]
__device__ float g_cw[T_DIM * C_DIM];               // chain weights [t][c]
__device__ float g_pow[11 * C_DIM * S_DIM * S_DIM]; // A^(2^k) [k][c][i][j]
__device__ float g_H0[C_DIM * S_DIM];

// ---------------- f32x2 helpers ----------------
typedef unsigned long long u64;
__device__ __forceinline__ u64 pack2(float x, float y) {
    u64 r; asm("mov.b64 %0, {%1,%2};" : "=l"(r) : "f"(x), "f"(y)); return r;
}
__device__ __forceinline__ float2 unpack2(u64 v) {
    float2 r; asm("mov.b64 {%0,%1}, %2;" : "=f"(r.x), "=f"(r.y) : "l"(v)); return r;
}
__device__ __forceinline__ u64 fma2(u64 a, u64 b, u64 c) {
    u64 d; asm("fma.rn.f32x2 %0, %1, %2, %3;" : "=l"(d) : "l"(a), "l"(b), "l"(c)); return d;
}

#define POW_FLOATS (11 * C_DIM * 256)   // 22528 floats = 90112 B

// ---------------- fused prep ----------------
__global__ void k_prep(const float* __restrict__ init_logits,
                       const float* __restrict__ tr_logits,
                       const float* __restrict__ cw_logits,
                       const float* __restrict__ em_logits) {
    extern __shared__ float sh[];
    int tid = threadIdx.x;
    int b = blockIdx.x;

    if (b == 0) {
        float* Ps = sh;
        if (tid < 128) {
            const float* row = tr_logits + tid * 16;
            float x[16]; float m = -1e30f;
            #pragma unroll
            for (int j = 0; j < 16; j++) { x[j] = row[j]; m = fmaxf(m, x[j]); }
            float s = 0.f;
            #pragma unroll
            for (int j = 0; j < 16; j++) { x[j] = __expf(x[j] - m); s += x[j]; }
            float inv = 1.0f / s;
            #pragma unroll
            for (int j = 0; j < 16; j++) Ps[tid * 16 + j] = x[j] * inv;
        } else if (tid < 136) {
            int c = tid - 128;
            const float* row = init_logits + c * 16;
            float x[16]; float m = -1e30f;
            #pragma unroll
            for (int j = 0; j < 16; j++) { x[j] = row[j]; m = fmaxf(m, x[j]); }
            float s = 0.f;
            #pragma unroll
            for (int j = 0; j < 16; j++) { x[j] = __expf(x[j] - m); s += x[j]; }
            float inv = 1.0f / s;
            #pragma unroll
            for (int j = 0; j < 16; j++) g_H0[c * 16 + j] = x[j] * inv;
        }
        __syncthreads();
        for (int k = 1; k < 11; k++) {
            for (int e = tid; e < C_DIM * 256; e += 256) {
                int c = e >> 8, ij = e & 255, i = ij >> 4, j = ij & 15;
                const float* P = Ps + (k - 1) * C_DIM * 256 + c * 256;
                float s = 0.f;
                #pragma unroll
                for (int m2 = 0; m2 < 16; m2++) s += P[i * 16 + m2] * P[m2 * 16 + j];
                Ps[k * C_DIM * 256 + c * 256 + ij] = s;
            }
            __syncthreads();
        }
        float4* dst = (float4*)g_pow;
        const float4* src = (const float4*)Ps;
        for (int idx = tid; idx < POW_FLOATS / 4; idx += 256) dst[idx] = src[idx];
    } else if (b <= 8) {
        int t = (b - 1) * 256 + tid;
        float x[8]; float m = -1e30f;
        #pragma unroll
        for (int c = 0; c < 8; c++) { x[c] = cw_logits[t * 8 + c]; m = fmaxf(m, x[c]); }
        float s = 0.f;
        #pragma unroll
        for (int c = 0; c < 8; c++) { x[c] = __expf(x[c] - m); s += x[c]; }
        float inv = 1.0f / s;
        #pragma unroll
        for (int c = 0; c < 8; c++) g_cw[t * 8 + c] = x[c] * inv;
    } else {
        float* red = sh;
        int row = b - 9;
        const float* src = em_logits + (size_t)row * N_DIM;
        float m = -1e30f, s = 0.f;
        for (int n = tid; n < N_DIM; n += 256) {
            float x = src[n];
            float nm = fmaxf(m, x);
            s = s * __expf(m - nm) + __expf(x - nm);
            m = nm;
        }
        red[tid] = m; red[256 + tid] = s; __syncthreads();
        for (int o = 128; o; o >>= 1) {
            if (tid < o) {
                float m1 = red[tid],      s1 = red[256 + tid];
                float m2 = red[tid + o],  s2 = red[256 + tid + o];
                float M = fmaxf(m1, m2);
                red[256 + tid] = s1 * __expf(m1 - M) + s2 * __expf(m2 - M);
                red[tid] = M;
            }
            __syncthreads();
        }
        float lse = red[0] + __logf(red[256]);
        float* dst = g_E + (size_t)row * N_DIM;
        for (int n = tid; n < N_DIM; n += 256) dst[n] = __expf(src[n] - lse);
    }
}

// ---------------- k_H: warp-coop binary decomposition ----------------
__global__ void __launch_bounds__(256) k_H(float* __restrict__ out_hidden) {
    int tid = threadIdx.x;
    int w = tid >> 5;
    int lane = tid & 31;
    int s = lane & 15;

    int d = blockIdx.x * 8 + w;
    int tA = (d >> 2) * 2;
    int tB = tA + 1;
    int c = 2 * (d & 3) + (lane >> 4);

    float h0v = g_H0[c * 16 + s];
    float hA = h0v, hB = h0v;

    #pragma unroll
    for (int k = 0; k < 11; k++) {
        int bA = (tA >> k) & 1;
        int bB = (tB >> k) & 1;
        if (bA | bB) {
            const float* P = g_pow + (k * 8 + c) * 256;
            float pcol[16];
            #pragma unroll
            for (int i = 0; i < 16; i++) pcol[i] = P[i * 16 + s];
            if (bA) {
                float n0 = 0.f, n1 = 0.f;
                #pragma unroll
                for (int i = 0; i < 8; i++) {
                    n0 = fmaf(__shfl_sync(0xffffffffu, hA, 2 * i,     16), pcol[2 * i],     n0);
                    n1 = fmaf(__shfl_sync(0xffffffffu, hA, 2 * i + 1, 16), pcol[2 * i + 1], n1);
                }
                hA = n0 + n1;
            }
            if (bB) {
                float n0 = 0.f, n1 = 0.f;
                #pragma unroll
                for (int i = 0; i < 8; i++) {
                    n0 = fmaf(__shfl_sync(0xffffffffu, hB, 2 * i,     16), pcol[2 * i],     n0);
                    n1 = fmaf(__shfl_sync(0xffffffffu, hB, 2 * i + 1, 16), pcol[2 * i + 1], n1);
                }
                hB = n0 + n1;
            }
        }
    }
    int idxA = (tA * 8 + c) * 16 + s;
    int idxB = (tB * 8 + c) * 16 + s;
    g_H[idxA] = hA;
    g_H[idxB] = hB;
    if (out_hidden) { out_hidden[idxA] = __logf(hA); out_hidden[idxB] = __logf(hB); }
}

// dummy to align ncu capture (absolute launch index 3 = k_main)
__global__ void k_nop() {}

// ---------------- k_main: tile 32n x 64t, 50KB smem, 4 blocks/SM ----------------
// nq = tid&7 (n-quad of 4), tg = tid>>3 (32 groups x 2 t).
// Warp = 8 nq x 4 tg -> ev LDS dedups to 1 phase; stores 4x128B segments.
__global__ void __launch_bounds__(256, 4)
k_main(float* __restrict__ out_obs, float* __restrict__ out_obs_c) {
    __shared__ float Es[128 * NT];     // [128 rows][32 n] = 16KB
    __shared__ float Hs[TT * 128];     // [64 t][8c][16s]  = 32KB
    __shared__ float CWs[TT * 8];      // 2KB
    int tid = threadIdx.x;
    int n0 = blockIdx.x * NT;
    int t0 = blockIdx.y * TT;

    // E tile (zero-fill OOB n): 128 rows x 32 n
    float4* Es4 = (float4*)Es;
    for (int idx = tid; idx < 128 * 8; idx += 256) {
        int r = idx >> 3, q = idx & 7;
        int n = n0 + q * 4;
        float4 v = make_float4(0.f, 0.f, 0.f, 0.f);
        if (n < N_DIM) v = *(const float4*)(g_E + (size_t)r * N_DIM + n);
        Es4[idx] = v;
    }
    // H tile
    {
        const float4* src = (const float4*)(g_H + t0 * 128);
        float4* dst = (float4*)Hs;
        for (int idx = tid; idx < 2048; idx += 256) dst[idx] = src[idx];
    }
    for (int idx = tid; idx < 512; idx += 256) CWs[idx] = g_cw[t0 * 8 + idx];
    __syncthreads();

    int nq = tid & 7;
    int tg = tid >> 3;
    int tl0 = tg * 2;
    int nvalid = (n0 + nq * 4) < N_DIM;

    u64 wsum[2][2];
    #pragma unroll
    for (int a = 0; a < 2; a++) { wsum[a][0] = 0ULL; wsum[a][1] = 0ULL; }

    const ulonglong2* Es2 = (const ulonglong2*)Es;  // row = 32 floats = 8 ulonglong2

    #pragma unroll 1
    for (int c = 0; c < 8; c++) {
        u64 acc[2][2];
        #pragma unroll
        for (int a = 0; a < 2; a++) { acc[a][0] = 0ULL; acc[a][1] = 0ULL; }

        #pragma unroll
        for (int sq = 0; sq < 4; sq++) {
            ulonglong2 ev[4];
            #pragma unroll
            for (int si = 0; si < 4; si++)
                ev[si] = Es2[(c * 16 + sq * 4 + si) * 8 + nq];
            #pragma unroll
            for (int tt = 0; tt < 2; tt++) {
                float4 hv = *(const float4*)(Hs + (tl0 + tt) * 128 + c * 16 + sq * 4);
                #pragma unroll
                for (int si = 0; si < 4; si++) {
                    float hsc = ((const float*)&hv)[si];
                    u64 hh = pack2(hsc, hsc);
                    acc[tt][0] = fma2(hh, ev[si].x, acc[tt][0]);
                    acc[tt][1] = fma2(hh, ev[si].y, acc[tt][1]);
                }
            }
        }
        #pragma unroll
        for (int tt = 0; tt < 2; tt++) {
            float cw = CWs[(tl0 + tt) * 8 + c];
            u64 cwp = pack2(cw, cw);
            wsum[tt][0] = fma2(cwp, acc[tt][0], wsum[tt][0]);
            wsum[tt][1] = fma2(cwp, acc[tt][1], wsum[tt][1]);
            if (out_obs_c && nvalid) {
                float2 p0 = unpack2(acc[tt][0]);
                float2 p1 = unpack2(acc[tt][1]);
                float4 o = make_float4(__logf(p0.x), __logf(p0.y), __logf(p1.x), __logf(p1.y));
                int t = t0 + tl0 + tt;
                *(float4*)(out_obs_c + (size_t)(t * 8 + c) * N_DIM + n0 + nq * 4) = o;
            }
        }
    }
    // store log_obs
    #pragma unroll
    for (int tt = 0; tt < 2; tt++) {
        if (nvalid) {
            float2 p0 = unpack2(wsum[tt][0]);
            float2 p1 = unpack2(wsum[tt][1]);
            float4 o = make_float4(__logf(p0.x), __logf(p0.y), __logf(p1.x), __logf(p1.y));
            int t = t0 + tl0 + tt;
            *(float4*)(out_obs + (size_t)t * N_DIM + n0 + nq * 4) = o;
        }
    }
}

// ---------------- launch ----------------
extern "C" void kernel_launch(void* const* d_in, const int* in_sizes, int n_in,
                              void* d_out, int out_size) {
    const float* cw_logits   = (const float*)d_in[0];  // (T, C)
    const float* init_logits = (const float*)d_in[1];  // (C, S)
    const float* em_logits   = (const float*)d_in[2];  // (C, S, N)
    const float* tr_logits   = (const float*)d_in[3];  // (C, S, S)
    float* out = (float*)d_out;

    const long long s0 = (long long)T_DIM * N_DIM;
    const long long s1 = (long long)T_DIM * C_DIM * N_DIM;
    const long long s2 = (long long)T_DIM * C_DIM * S_DIM;
    long long osz = (long long)out_size;

    float* out_obs    = out;
    float* out_obs_c  = (osz >= s0 + s1)      ? out + s0      : nullptr;
    float* out_hidden = (osz >= s0 + s1 + s2) ? out + s0 + s1 : nullptr;

    const int prep_smem = POW_FLOATS * 4;   // 90112
    cudaFuncSetAttribute(k_prep, cudaFuncAttributeMaxDynamicSharedMemorySize, prep_smem);

    k_prep<<<9 + C_DIM * S_DIM, 256, prep_smem>>>(init_logits, tr_logits, cw_logits, em_logits);
    k_H<<<512, 256>>>(out_hidden);
    k_nop<<<1, 32>>>();   // aligns ncu capture (index 3) onto k_main

    dim3 grid((N_DIM + NT - 1) / NT, T_DIM / TT);
    k_main<<<grid, 256>>>(out_obs, out_obs_c);
}

// round 10
// speedup vs baseline: 2.4723x; 2.4723x over previous
#include <cuda_runtime.h>
#include <math.h>

#define T_DIM 2048
#define C_DIM 8
#define S_DIM 16
#define N_DIM 10000
#define NT 64
#define TT 64

// ---------------- scratch ----------------
__device__ float g_E[C_DIM * S_DIM * N_DIM];        // emission probs [c][s][n]
__device__ float g_H[T_DIM * C_DIM * S_DIM];        // hidden probs [t][c][s]
__device__ float g_cw[T_DIM * C_DIM];               // chain weights [t][c]
__device__ float g_pow[11 * C_DIM * S_DIM * S_DIM]; // A^(2^k) [k][c][i][j]
__device__ float g_H0[C_DIM * S_DIM];

// ---------------- f32x2 helpers ----------------
typedef unsigned long long u64;
__device__ __forceinline__ u64 pack2(float x, float y) {
    u64 r; asm("mov.b64 %0, {%1,%2};" : "=l"(r) : "f"(x), "f"(y)); return r;
}
__device__ __forceinline__ float2 unpack2(u64 v) {
    float2 r; asm("mov.b64 {%0,%1}, %2;" : "=f"(r.x), "=f"(r.y) : "l"(v)); return r;
}
__device__ __forceinline__ u64 fma2(u64 a, u64 b, u64 c) {
    u64 d; asm("fma.rn.f32x2 %0, %1, %2, %3;" : "=l"(d) : "l"(a), "l"(b), "l"(c)); return d;
}
// streaming (evict-first) 128-bit store
__device__ __forceinline__ void stg_cs(float* p, float4 v) {
    asm volatile("st.global.cs.v4.f32 [%0], {%1,%2,%3,%4};"
                 :: "l"(p), "f"(v.x), "f"(v.y), "f"(v.z), "f"(v.w) : "memory");
}

#define POW_FLOATS (11 * C_DIM * 256)   // 22528 floats = 90112 B

// ---------------- fused prep ----------------
__global__ void k_prep(const float* __restrict__ init_logits,
                       const float* __restrict__ tr_logits,
                       const float* __restrict__ cw_logits,
                       const float* __restrict__ em_logits) {
    extern __shared__ float sh[];
    int tid = threadIdx.x;
    int b = blockIdx.x;

    if (b == 0) {
        float* Ps = sh;
        if (tid < 128) {
            const float* row = tr_logits + tid * 16;
            float x[16]; float m = -1e30f;
            #pragma unroll
            for (int j = 0; j < 16; j++) { x[j] = row[j]; m = fmaxf(m, x[j]); }
            float s = 0.f;
            #pragma unroll
            for (int j = 0; j < 16; j++) { x[j] = __expf(x[j] - m); s += x[j]; }
            float inv = 1.0f / s;
            #pragma unroll
            for (int j = 0; j < 16; j++) Ps[tid * 16 + j] = x[j] * inv;
        } else if (tid < 136) {
            int c = tid - 128;
            const float* row = init_logits + c * 16;
            float x[16]; float m = -1e30f;
            #pragma unroll
            for (int j = 0; j < 16; j++) { x[j] = row[j]; m = fmaxf(m, x[j]); }
            float s = 0.f;
            #pragma unroll
            for (int j = 0; j < 16; j++) { x[j] = __expf(x[j] - m); s += x[j]; }
            float inv = 1.0f / s;
            #pragma unroll
            for (int j = 0; j < 16; j++) g_H0[c * 16 + j] = x[j] * inv;
        }
        __syncthreads();
        for (int k = 1; k < 11; k++) {
            for (int e = tid; e < C_DIM * 256; e += 256) {
                int c = e >> 8, ij = e & 255, i = ij >> 4, j = ij & 15;
                const float* P = Ps + (k - 1) * C_DIM * 256 + c * 256;
                float s = 0.f;
                #pragma unroll
                for (int m2 = 0; m2 < 16; m2++) s += P[i * 16 + m2] * P[m2 * 16 + j];
                Ps[k * C_DIM * 256 + c * 256 + ij] = s;
            }
            __syncthreads();
        }
        float4* dst = (float4*)g_pow;
        const float4* src = (const float4*)Ps;
        for (int idx = tid; idx < POW_FLOATS / 4; idx += 256) dst[idx] = src[idx];
    } else if (b <= 8) {
        int t = (b - 1) * 256 + tid;
        float x[8]; float m = -1e30f;
        #pragma unroll
        for (int c = 0; c < 8; c++) { x[c] = cw_logits[t * 8 + c]; m = fmaxf(m, x[c]); }
        float s = 0.f;
        #pragma unroll
        for (int c = 0; c < 8; c++) { x[c] = __expf(x[c] - m); s += x[c]; }
        float inv = 1.0f / s;
        #pragma unroll
        for (int c = 0; c < 8; c++) g_cw[t * 8 + c] = x[c] * inv;
    } else {
        float* red = sh;
        int row = b - 9;
        const float* src = em_logits + (size_t)row * N_DIM;
        float m = -1e30f, s = 0.f;
        for (int n = tid; n < N_DIM; n += 256) {
            float x = src[n];
            float nm = fmaxf(m, x);
            s = s * __expf(m - nm) + __expf(x - nm);
            m = nm;
        }
        red[tid] = m; red[256 + tid] = s; __syncthreads();
        for (int o = 128; o; o >>= 1) {
            if (tid < o) {
                float m1 = red[tid],      s1 = red[256 + tid];
                float m2 = red[tid + o],  s2 = red[256 + tid + o];
                float M = fmaxf(m1, m2);
                red[256 + tid] = s1 * __expf(m1 - M) + s2 * __expf(m2 - M);
                red[tid] = M;
            }
            __syncthreads();
        }
        float lse = red[0] + __logf(red[256]);
        float* dst = g_E + (size_t)row * N_DIM;
        for (int n = tid; n < N_DIM; n += 256) dst[n] = __expf(src[n] - lse);
    }
}

// ---------------- k_H: warp-coop binary decomposition ----------------
__global__ void __launch_bounds__(256) k_H(float* __restrict__ out_hidden) {
    int tid = threadIdx.x;
    int w = tid >> 5;
    int lane = tid & 31;
    int s = lane & 15;

    int d = blockIdx.x * 8 + w;
    int tA = (d >> 2) * 2;
    int tB = tA + 1;
    int c = 2 * (d & 3) + (lane >> 4);

    float h0v = g_H0[c * 16 + s];
    float hA = h0v, hB = h0v;

    #pragma unroll
    for (int k = 0; k < 11; k++) {
        int bA = (tA >> k) & 1;
        int bB = (tB >> k) & 1;
        if (bA | bB) {
            const float* P = g_pow + (k * 8 + c) * 256;
            float pcol[16];
            #pragma unroll
            for (int i = 0; i < 16; i++) pcol[i] = P[i * 16 + s];
            if (bA) {
                float n0 = 0.f, n1 = 0.f;
                #pragma unroll
                for (int i = 0; i < 8; i++) {
                    n0 = fmaf(__shfl_sync(0xffffffffu, hA, 2 * i,     16), pcol[2 * i],     n0);
                    n1 = fmaf(__shfl_sync(0xffffffffu, hA, 2 * i + 1, 16), pcol[2 * i + 1], n1);
                }
                hA = n0 + n1;
            }
            if (bB) {
                float n0 = 0.f, n1 = 0.f;
                #pragma unroll
                for (int i = 0; i < 8; i++) {
                    n0 = fmaf(__shfl_sync(0xffffffffu, hB, 2 * i,     16), pcol[2 * i],     n0);
                    n1 = fmaf(__shfl_sync(0xffffffffu, hB, 2 * i + 1, 16), pcol[2 * i + 1], n1);
                }
                hB = n0 + n1;
            }
        }
    }
    int idxA = (tA * 8 + c) * 16 + s;
    int idxB = (tB * 8 + c) * 16 + s;
    g_H[idxA] = hA;
    g_H[idxB] = hB;
    if (out_hidden) { out_hidden[idxA] = __logf(hA); out_hidden[idxB] = __logf(hB); }
}

// dummy to align ncu capture (absolute launch index 3 = k_main)
__global__ void k_nop() {}

// ---------------- k_main: R5 config (64n x 64t, 3 blocks/SM) + streaming stores ----------------
// nq = tid&15 (n-quad of 4), tg = tid>>4 (16 groups x 4 t).
__global__ void __launch_bounds__(256, 3)
k_main(float* __restrict__ out_obs, float* __restrict__ out_obs_c) {
    extern __shared__ float smem[];
    float* Es  = smem;                  // [128 rows][64 n] = 8192 f (32KB)
    float* Hs  = smem + 8192;           // [64 t][128]      = 8192 f (32KB)
    float* CWs = smem + 16384;          // [64 t][8 c]      = 512 f (2KB)
    int tid = threadIdx.x;
    int n0 = blockIdx.x * NT;
    int t0 = blockIdx.y * TT;

    // E tile (zero-fill OOB n): 128 rows x 64 n
    float4* Es4 = (float4*)Es;
    for (int idx = tid; idx < 128 * 16; idx += 256) {
        int r = idx >> 4, q = idx & 15;
        int n = n0 + q * 4;
        float4 v = make_float4(0.f, 0.f, 0.f, 0.f);
        if (n < N_DIM) v = *(const float4*)(g_E + (size_t)r * N_DIM + n);
        Es4[idx] = v;
    }
    // H tile
    {
        const float4* src = (const float4*)(g_H + t0 * 128);
        float4* dst = (float4*)Hs;
        for (int idx = tid; idx < 2048; idx += 256) dst[idx] = src[idx];
    }
    for (int idx = tid; idx < 512; idx += 256) CWs[idx] = g_cw[t0 * 8 + idx];
    __syncthreads();

    int nq = tid & 15;
    int tg = tid >> 4;
    int tl0 = tg * 4;
    int nvalid = (n0 + nq * 4) < N_DIM;

    u64 wsum[4][2];
    #pragma unroll
    for (int a = 0; a < 4; a++) { wsum[a][0] = 0ULL; wsum[a][1] = 0ULL; }

    const ulonglong2* Es2 = (const ulonglong2*)Es;  // row = 64 floats = 16 ulonglong2

    #pragma unroll 1
    for (int c = 0; c < 8; c++) {
        u64 acc[4][2];
        #pragma unroll
        for (int a = 0; a < 4; a++) { acc[a][0] = 0ULL; acc[a][1] = 0ULL; }
        #pragma unroll
        for (int sq = 0; sq < 4; sq++) {
            ulonglong2 ev[4];
            #pragma unroll
            for (int si = 0; si < 4; si++)
                ev[si] = Es2[(c * 16 + sq * 4 + si) * 16 + nq];
            #pragma unroll
            for (int tt = 0; tt < 4; tt++) {
                float4 hv = *(const float4*)(Hs + (tl0 + tt) * 128 + c * 16 + sq * 4);
                #pragma unroll
                for (int si = 0; si < 4; si++) {
                    float hsc = ((const float*)&hv)[si];
                    u64 hh = pack2(hsc, hsc);
                    acc[tt][0] = fma2(hh, ev[si].x, acc[tt][0]);
                    acc[tt][1] = fma2(hh, ev[si].y, acc[tt][1]);
                }
            }
        }
        #pragma unroll
        for (int tt = 0; tt < 4; tt++) {
            float cw = CWs[(tl0 + tt) * 8 + c];
            u64 cwp = pack2(cw, cw);
            wsum[tt][0] = fma2(cwp, acc[tt][0], wsum[tt][0]);
            wsum[tt][1] = fma2(cwp, acc[tt][1], wsum[tt][1]);
            if (out_obs_c && nvalid) {
                float2 p0 = unpack2(acc[tt][0]);
                float2 p1 = unpack2(acc[tt][1]);
                float4 o = make_float4(__logf(p0.x), __logf(p0.y), __logf(p1.x), __logf(p1.y));
                int t = t0 + tl0 + tt;
                stg_cs(out_obs_c + (size_t)(t * 8 + c) * N_DIM + n0 + nq * 4, o);
            }
        }
    }
    // store log_obs
    #pragma unroll
    for (int tt = 0; tt < 4; tt++) {
        if (nvalid) {
            float2 p0 = unpack2(wsum[tt][0]);
            float2 p1 = unpack2(wsum[tt][1]);
            float4 o = make_float4(__logf(p0.x), __logf(p0.y), __logf(p1.x), __logf(p1.y));
            int t = t0 + tl0 + tt;
            stg_cs(out_obs + (size_t)t * N_DIM + n0 + nq * 4, o);
        }
    }
}

// ---------------- launch ----------------
extern "C" void kernel_launch(void* const* d_in, const int* in_sizes, int n_in,
                              void* d_out, int out_size) {
    const float* cw_logits   = (const float*)d_in[0];  // (T, C)
    const float* init_logits = (const float*)d_in[1];  // (C, S)
    const float* em_logits   = (const float*)d_in[2];  // (C, S, N)
    const float* tr_logits   = (const float*)d_in[3];  // (C, S, S)
    float* out = (float*)d_out;

    const long long s0 = (long long)T_DIM * N_DIM;
    const long long s1 = (long long)T_DIM * C_DIM * N_DIM;
    const long long s2 = (long long)T_DIM * C_DIM * S_DIM;
    long long osz = (long long)out_size;

    float* out_obs    = out;
    float* out_obs_c  = (osz >= s0 + s1)      ? out + s0      : nullptr;
    float* out_hidden = (osz >= s0 + s1 + s2) ? out + s0 + s1 : nullptr;

    const int prep_smem = POW_FLOATS * 4;            // 90112
    const int main_smem = (8192 + 8192 + 512) * 4;   // 67584
    cudaFuncSetAttribute(k_prep, cudaFuncAttributeMaxDynamicSharedMemorySize, prep_smem);
    cudaFuncSetAttribute(k_main, cudaFuncAttributeMaxDynamicSharedMemorySize, main_smem);

    k_prep<<<9 + C_DIM * S_DIM, 256, prep_smem>>>(init_logits, tr_logits, cw_logits, em_logits);
    k_H<<<512, 256>>>(out_hidden);
    k_nop<<<1, 32>>>();   // aligns ncu capture (index 3) onto k_main

    dim3 grid((N_DIM + NT - 1) / NT, T_DIM / TT);
    k_main<<<grid, 256, main_smem>>>(out_obs, out_obs_c);
}

// round 11
// speedup vs baseline: 2.5069x; 1.0140x over previous
#include <cuda_runtime.h>
#include <math.h>

#define T_DIM 2048
#define C_DIM 8
#define S_DIM 16
#define N_DIM 10000
#define NT 128
#define TT 64

// ---------------- scratch ----------------
__device__ float g_E[C_DIM * S_DIM * N_DIM];        // emission probs [c][s][n]
__device__ float g_H[T_DIM * C_DIM * S_DIM];        // hidden probs [t][c][s]
__device__ float g_cw[T_DIM * C_DIM];               // chain weights [t][c]
__device__ float g_pow[11 * C_DIM * S_DIM * S_DIM]; // A^(2^k) [k][c][i][j]
__device__ float g_H0[C_DIM * S_DIM];

// ---------------- f32x2 helpers ----------------
typedef unsigned long long u64;
__device__ __forceinline__ u64 pack2(float x, float y) {
    u64 r; asm("mov.b64 %0, {%1,%2};" : "=l"(r) : "f"(x), "f"(y)); return r;
}
__device__ __forceinline__ float2 unpack2(u64 v) {
    float2 r; asm("mov.b64 {%0,%1}, %2;" : "=f"(r.x), "=f"(r.y) : "l"(v)); return r;
}
__device__ __forceinline__ u64 fma2(u64 a, u64 b, u64 c) {
    u64 d; asm("fma.rn.f32x2 %0, %1, %2, %3;" : "=l"(d) : "l"(a), "l"(b), "l"(c)); return d;
}
// streaming (evict-first) 128-bit store
__device__ __forceinline__ void stg_cs(float* p, float4 v) {
    asm volatile("st.global.cs.v4.f32 [%0], {%1,%2,%3,%4};"
                 :: "l"(p), "f"(v.x), "f"(v.y), "f"(v.z), "f"(v.w) : "memory");
}

#define POW_FLOATS (11 * C_DIM * 256)   // 22528 floats = 90112 B

// ---------------- fused prep ----------------
__global__ void k_prep(const float* __restrict__ init_logits,
                       const float* __restrict__ tr_logits,
                       const float* __restrict__ cw_logits,
                       const float* __restrict__ em_logits) {
    extern __shared__ float sh[];
    int tid = threadIdx.x;
    int b = blockIdx.x;

    if (b == 0) {
        float* Ps = sh;
        if (tid < 128) {
            const float* row = tr_logits + tid * 16;
            float x[16]; float m = -1e30f;
            #pragma unroll
            for (int j = 0; j < 16; j++) { x[j] = row[j]; m = fmaxf(m, x[j]); }
            float s = 0.f;
            #pragma unroll
            for (int j = 0; j < 16; j++) { x[j] = __expf(x[j] - m); s += x[j]; }
            float inv = 1.0f / s;
            #pragma unroll
            for (int j = 0; j < 16; j++) Ps[tid * 16 + j] = x[j] * inv;
        } else if (tid < 136) {
            int c = tid - 128;
            const float* row = init_logits + c * 16;
            float x[16]; float m = -1e30f;
            #pragma unroll
            for (int j = 0; j < 16; j++) { x[j] = row[j]; m = fmaxf(m, x[j]); }
            float s = 0.f;
            #pragma unroll
            for (int j = 0; j < 16; j++) { x[j] = __expf(x[j] - m); s += x[j]; }
            float inv = 1.0f / s;
            #pragma unroll
            for (int j = 0; j < 16; j++) g_H0[c * 16 + j] = x[j] * inv;
        }
        __syncthreads();
        for (int k = 1; k < 11; k++) {
            for (int e = tid; e < C_DIM * 256; e += 256) {
                int c = e >> 8, ij = e & 255, i = ij >> 4, j = ij & 15;
                const float* P = Ps + (k - 1) * C_DIM * 256 + c * 256;
                float s = 0.f;
                #pragma unroll
                for (int m2 = 0; m2 < 16; m2++) s += P[i * 16 + m2] * P[m2 * 16 + j];
                Ps[k * C_DIM * 256 + c * 256 + ij] = s;
            }
            __syncthreads();
        }
        float4* dst = (float4*)g_pow;
        const float4* src = (const float4*)Ps;
        for (int idx = tid; idx < POW_FLOATS / 4; idx += 256) dst[idx] = src[idx];
    } else if (b <= 8) {
        int t = (b - 1) * 256 + tid;
        float x[8]; float m = -1e30f;
        #pragma unroll
        for (int c = 0; c < 8; c++) { x[c] = cw_logits[t * 8 + c]; m = fmaxf(m, x[c]); }
        float s = 0.f;
        #pragma unroll
        for (int c = 0; c < 8; c++) { x[c] = __expf(x[c] - m); s += x[c]; }
        float inv = 1.0f / s;
        #pragma unroll
        for (int c = 0; c < 8; c++) g_cw[t * 8 + c] = x[c] * inv;
    } else {
        // ---- emission softmax over N, float4 I/O (N=10000 = 2500 float4) ----
        float* red = sh;
        int row = b - 9;
        const float4* src4 = (const float4*)(em_logits + (size_t)row * N_DIM);
        float m = -1e30f, s = 0.f;
        for (int q = tid; q < 2500; q += 256) {
            float4 v = src4[q];
            float m01 = fmaxf(v.x, v.y), m23 = fmaxf(v.z, v.w);
            float mv = fmaxf(m01, m23);
            float nm = fmaxf(m, mv);
            float sc = __expf(m - nm);
            s = s * sc + __expf(v.x - nm) + __expf(v.y - nm)
                       + __expf(v.z - nm) + __expf(v.w - nm);
            m = nm;
        }
        red[tid] = m; red[256 + tid] = s; __syncthreads();
        for (int o = 128; o; o >>= 1) {
            if (tid < o) {
                float m1 = red[tid],      s1 = red[256 + tid];
                float m2 = red[tid + o],  s2 = red[256 + tid + o];
                float M = fmaxf(m1, m2);
                red[256 + tid] = s1 * __expf(m1 - M) + s2 * __expf(m2 - M);
                red[tid] = M;
            }
            __syncthreads();
        }
        float lse = red[0] + __logf(red[256]);
        float4* dst4 = (float4*)(g_E + (size_t)row * N_DIM);
        for (int q = tid; q < 2500; q += 256) {
            float4 v = src4[q];
            float4 o;
            o.x = __expf(v.x - lse); o.y = __expf(v.y - lse);
            o.z = __expf(v.z - lse); o.w = __expf(v.w - lse);
            dst4[q] = o;
        }
    }
}

// ---------------- k_H: warp-coop binary decomposition ----------------
__global__ void __launch_bounds__(256) k_H(float* __restrict__ out_hidden) {
    int tid = threadIdx.x;
    int w = tid >> 5;
    int lane = tid & 31;
    int s = lane & 15;

    int d = blockIdx.x * 8 + w;
    int tA = (d >> 2) * 2;
    int tB = tA + 1;
    int c = 2 * (d & 3) + (lane >> 4);

    float h0v = g_H0[c * 16 + s];
    float hA = h0v, hB = h0v;

    #pragma unroll
    for (int k = 0; k < 11; k++) {
        int bA = (tA >> k) & 1;
        int bB = (tB >> k) & 1;
        if (bA | bB) {
            const float* P = g_pow + (k * 8 + c) * 256;
            float pcol[16];
            #pragma unroll
            for (int i = 0; i < 16; i++) pcol[i] = P[i * 16 + s];
            if (bA) {
                float n0 = 0.f, n1 = 0.f;
                #pragma unroll
                for (int i = 0; i < 8; i++) {
                    n0 = fmaf(__shfl_sync(0xffffffffu, hA, 2 * i,     16), pcol[2 * i],     n0);
                    n1 = fmaf(__shfl_sync(0xffffffffu, hA, 2 * i + 1, 16), pcol[2 * i + 1], n1);
                }
                hA = n0 + n1;
            }
            if (bB) {
                float n0 = 0.f, n1 = 0.f;
                #pragma unroll
                for (int i = 0; i < 8; i++) {
                    n0 = fmaf(__shfl_sync(0xffffffffu, hB, 2 * i,     16), pcol[2 * i],     n0);
                    n1 = fmaf(__shfl_sync(0xffffffffu, hB, 2 * i + 1, 16), pcol[2 * i + 1], n1);
                }
                hB = n0 + n1;
            }
        }
    }
    int idxA = (tA * 8 + c) * 16 + s;
    int idxB = (tB * 8 + c) * 16 + s;
    g_H[idxA] = hA;
    g_H[idxB] = hB;
    if (out_hidden) { out_hidden[idxA] = __logf(hA); out_hidden[idxB] = __logf(hB); }
}

// dummy to align ncu capture (absolute launch index 3 = k_main)
__global__ void k_nop() {}

// ---------------- k_main: 128n x 64t, 8t/thread, warp-uniform tg, stg.cs ----------------
// nq = tid&31 (n-quad of 4), tg = tid>>5 (8 warps x 8 t). hv loads are warp-broadcast.
__global__ void __launch_bounds__(256, 2)
k_main(float* __restrict__ out_obs, float* __restrict__ out_obs_c) {
    extern __shared__ float smem[];
    float* Es  = smem;                    // [128 rows][128 n] = 16384 f (64KB)
    float* Hs  = smem + 16384;            // [64 t][128]       = 8192 f (32KB)
    float* CWs = smem + 16384 + 8192;     // [64 t][8 c]       = 512 f (2KB)
    int tid = threadIdx.x;
    int n0 = blockIdx.x * NT;
    int t0 = blockIdx.y * TT;

    // E tile (zero-fill OOB n): 128 rows x 128 n
    float4* Es4 = (float4*)Es;
    for (int idx = tid; idx < 128 * 32; idx += 256) {
        int r = idx >> 5, q = idx & 31;
        int n = n0 + q * 4;
        float4 v = make_float4(0.f, 0.f, 0.f, 0.f);
        if (n < N_DIM) v = *(const float4*)(g_E + (size_t)r * N_DIM + n);
        Es4[idx] = v;
    }
    // H tile
    {
        const float4* src = (const float4*)(g_H + t0 * 128);
        float4* dst = (float4*)Hs;
        for (int idx = tid; idx < 2048; idx += 256) dst[idx] = src[idx];
    }
    for (int idx = tid; idx < 512; idx += 256) CWs[idx] = g_cw[t0 * 8 + idx];
    __syncthreads();

    int nq = tid & 31;        // n-quad (warp-varying)
    int tg = tid >> 5;        // warp id = t-group (8 t each, warp-uniform)
    int tl0 = tg * 8;
    int nvalid = (n0 + nq * 4) < N_DIM;

    u64 wsum[8][2];
    #pragma unroll
    for (int a = 0; a < 8; a++) { wsum[a][0] = 0ULL; wsum[a][1] = 0ULL; }

    const ulonglong2* Es2 = (const ulonglong2*)Es;  // row = 128 floats = 32 ulonglong2

    #pragma unroll 1
    for (int c = 0; c < 8; c++) {
        u64 acc[8][2];
        #pragma unroll
        for (int a = 0; a < 8; a++) { acc[a][0] = 0ULL; acc[a][1] = 0ULL; }
        #pragma unroll
        for (int sq = 0; sq < 4; sq++) {
            ulonglong2 ev[4];
            #pragma unroll
            for (int si = 0; si < 4; si++)
                ev[si] = Es2[(c * 16 + sq * 4 + si) * 32 + nq];
            #pragma unroll
            for (int tt = 0; tt < 8; tt++) {
                float4 hv = *(const float4*)(Hs + (tl0 + tt) * 128 + c * 16 + sq * 4);
                #pragma unroll
                for (int si = 0; si < 4; si++) {
                    float hsc = ((const float*)&hv)[si];
                    u64 hh = pack2(hsc, hsc);
                    acc[tt][0] = fma2(hh, ev[si].x, acc[tt][0]);
                    acc[tt][1] = fma2(hh, ev[si].y, acc[tt][1]);
                }
            }
        }
        // per-c epilogue: weight-accumulate + store log_obs_
        #pragma unroll
        for (int tt = 0; tt < 8; tt++) {
            float cw = CWs[(tl0 + tt) * 8 + c];
            u64 cwp = pack2(cw, cw);
            wsum[tt][0] = fma2(cwp, acc[tt][0], wsum[tt][0]);
            wsum[tt][1] = fma2(cwp, acc[tt][1], wsum[tt][1]);
            if (out_obs_c && nvalid) {
                float2 p0 = unpack2(acc[tt][0]);
                float2 p1 = unpack2(acc[tt][1]);
                float4 o = make_float4(__logf(p0.x), __logf(p0.y), __logf(p1.x), __logf(p1.y));
                int t = t0 + tl0 + tt;
                stg_cs(out_obs_c + (size_t)(t * 8 + c) * N_DIM + n0 + nq * 4, o);
            }
        }
    }
    // store log_obs
    #pragma unroll
    for (int tt = 0; tt < 8; tt++) {
        if (nvalid) {
            float2 p0 = unpack2(wsum[tt][0]);
            float2 p1 = unpack2(wsum[tt][1]);
            float4 o = make_float4(__logf(p0.x), __logf(p0.y), __logf(p1.x), __logf(p1.y));
            int t = t0 + tl0 + tt;
            stg_cs(out_obs + (size_t)t * N_DIM + n0 + nq * 4, o);
        }
    }
}

// ---------------- launch ----------------
extern "C" void kernel_launch(void* const* d_in, const int* in_sizes, int n_in,
                              void* d_out, int out_size) {
    const float* cw_logits   = (const float*)d_in[0];  // (T, C)
    const float* init_logits = (const float*)d_in[1];  // (C, S)
    const float* em_logits   = (const float*)d_in[2];  // (C, S, N)
    const float* tr_logits   = (const float*)d_in[3];  // (C, S, S)
    float* out = (float*)d_out;

    const long long s0 = (long long)T_DIM * N_DIM;
    const long long s1 = (long long)T_DIM * C_DIM * N_DIM;
    const long long s2 = (long long)T_DIM * C_DIM * S_DIM;
    long long osz = (long long)out_size;

    float* out_obs    = out;
    float* out_obs_c  = (osz >= s0 + s1)      ? out + s0      : nullptr;
    float* out_hidden = (osz >= s0 + s1 + s2) ? out + s0 + s1 : nullptr;

    const int prep_smem = POW_FLOATS * 4;              // 90112
    const int main_smem = (16384 + 8192 + 512) * 4;    // 100352
    cudaFuncSetAttribute(k_prep, cudaFuncAttributeMaxDynamicSharedMemorySize, prep_smem);
    cudaFuncSetAttribute(k_main, cudaFuncAttributeMaxDynamicSharedMemorySize, main_smem);

    k_prep<<<9 + C_DIM * S_DIM, 256, prep_smem>>>(init_logits, tr_logits, cw_logits, em_logits);
    k_H<<<512, 256>>>(out_hidden);
    k_nop<<<1, 32>>>();   // aligns ncu capture (index 3) onto k_main

    dim3 grid((N_DIM + NT - 1) / NT, T_DIM / TT);
    k_main<<<grid, 256, main_smem>>>(out_obs, out_obs_c);
}

// round 12
// speedup vs baseline: 2.6099x; 1.0411x over previous
#include <cuda_runtime.h>
#include <math.h>

#define T_DIM 2048
#define C_DIM 8
#define S_DIM 16
#define N_DIM 10000
#define NT 128
#define TT 64

// ---------------- scratch ----------------
__device__ float g_E[C_DIM * S_DIM * N_DIM];        // emission probs [c][s][n]
__device__ float g_H[T_DIM * C_DIM * S_DIM];        // hidden probs [t][c][s]
__device__ float g_cw[T_DIM * C_DIM];               // chain weights [t][c]
__device__ float g_pow[11 * C_DIM * S_DIM * S_DIM]; // A^(2^k) [k][c][i][j]
__device__ float g_H0[C_DIM * S_DIM];

// ---------------- f32x2 helpers ----------------
typedef unsigned long long u64;
__device__ __forceinline__ u64 pack2(float x, float y) {
    u64 r; asm("mov.b64 %0, {%1,%2};" : "=l"(r) : "f"(x), "f"(y)); return r;
}
__device__ __forceinline__ float2 unpack2(u64 v) {
    float2 r; asm("mov.b64 {%0,%1}, %2;" : "=f"(r.x), "=f"(r.y) : "l"(v)); return r;
}
__device__ __forceinline__ u64 fma2(u64 a, u64 b, u64 c) {
    u64 d; asm("fma.rn.f32x2 %0, %1, %2, %3;" : "=l"(d) : "l"(a), "l"(b), "l"(c)); return d;
}
// streaming (evict-first) 128-bit store
__device__ __forceinline__ void stg_cs(float* p, float4 v) {
    asm volatile("st.global.cs.v4.f32 [%0], {%1,%2,%3,%4};"
                 :: "l"(p), "f"(v.x), "f"(v.y), "f"(v.z), "f"(v.w) : "memory");
}

#define POW_FLOATS (11 * C_DIM * 256)   // 22528 floats = 90112 B

// ---------------- fused prep ----------------
__global__ void k_prep(const float* __restrict__ init_logits,
                       const float* __restrict__ tr_logits,
                       const float* __restrict__ cw_logits,
                       const float* __restrict__ em_logits) {
    extern __shared__ float sh[];
    int tid = threadIdx.x;
    int b = blockIdx.x;

    if (b == 0) {
        float* Ps = sh;
        if (tid < 128) {
            const float* row = tr_logits + tid * 16;
            float x[16]; float m = -1e30f;
            #pragma unroll
            for (int j = 0; j < 16; j++) { x[j] = row[j]; m = fmaxf(m, x[j]); }
            float s = 0.f;
            #pragma unroll
            for (int j = 0; j < 16; j++) { x[j] = __expf(x[j] - m); s += x[j]; }
            float inv = 1.0f / s;
            #pragma unroll
            for (int j = 0; j < 16; j++) Ps[tid * 16 + j] = x[j] * inv;
        } else if (tid < 136) {
            int c = tid - 128;
            const float* row = init_logits + c * 16;
            float x[16]; float m = -1e30f;
            #pragma unroll
            for (int j = 0; j < 16; j++) { x[j] = row[j]; m = fmaxf(m, x[j]); }
            float s = 0.f;
            #pragma unroll
            for (int j = 0; j < 16; j++) { x[j] = __expf(x[j] - m); s += x[j]; }
            float inv = 1.0f / s;
            #pragma unroll
            for (int j = 0; j < 16; j++) g_H0[c * 16 + j] = x[j] * inv;
        }
        __syncthreads();
        for (int k = 1; k < 11; k++) {
            for (int e = tid; e < C_DIM * 256; e += 256) {
                int c = e >> 8, ij = e & 255, i = ij >> 4, j = ij & 15;
                const float* P = Ps + (k - 1) * C_DIM * 256 + c * 256;
                float s = 0.f;
                #pragma unroll
                for (int m2 = 0; m2 < 16; m2++) s += P[i * 16 + m2] * P[m2 * 16 + j];
                Ps[k * C_DIM * 256 + c * 256 + ij] = s;
            }
            __syncthreads();
        }
        float4* dst = (float4*)g_pow;
        const float4* src = (const float4*)Ps;
        for (int idx = tid; idx < POW_FLOATS / 4; idx += 256) dst[idx] = src[idx];
    } else if (b <= 8) {
        int t = (b - 1) * 256 + tid;
        float x[8]; float m = -1e30f;
        #pragma unroll
        for (int c = 0; c < 8; c++) { x[c] = cw_logits[t * 8 + c]; m = fmaxf(m, x[c]); }
        float s = 0.f;
        #pragma unroll
        for (int c = 0; c < 8; c++) { x[c] = __expf(x[c] - m); s += x[c]; }
        float inv = 1.0f / s;
        #pragma unroll
        for (int c = 0; c < 8; c++) g_cw[t * 8 + c] = x[c] * inv;
    } else {
        // emission softmax over N, float4 I/O (N=10000 = 2500 float4)
        float* red = sh;
        int row = b - 9;
        const float4* src4 = (const float4*)(em_logits + (size_t)row * N_DIM);
        float m = -1e30f, s = 0.f;
        for (int q = tid; q < 2500; q += 256) {
            float4 v = src4[q];
            float m01 = fmaxf(v.x, v.y), m23 = fmaxf(v.z, v.w);
            float mv = fmaxf(m01, m23);
            float nm = fmaxf(m, mv);
            float sc = __expf(m - nm);
            s = s * sc + __expf(v.x - nm) + __expf(v.y - nm)
                       + __expf(v.z - nm) + __expf(v.w - nm);
            m = nm;
        }
        red[tid] = m; red[256 + tid] = s; __syncthreads();
        for (int o = 128; o; o >>= 1) {
            if (tid < o) {
                float m1 = red[tid],      s1 = red[256 + tid];
                float m2 = red[tid + o],  s2 = red[256 + tid + o];
                float M = fmaxf(m1, m2);
                red[256 + tid] = s1 * __expf(m1 - M) + s2 * __expf(m2 - M);
                red[tid] = M;
            }
            __syncthreads();
        }
        float lse = red[0] + __logf(red[256]);
        float4* dst4 = (float4*)(g_E + (size_t)row * N_DIM);
        for (int q = tid; q < 2500; q += 256) {
            float4 v = src4[q];
            float4 o;
            o.x = __expf(v.x - lse); o.y = __expf(v.y - lse);
            o.z = __expf(v.z - lse); o.w = __expf(v.w - lse);
            dst4[q] = o;
        }
    }
}

// ---------------- k_H: warp-coop binary decomposition ----------------
__global__ void __launch_bounds__(256) k_H(float* __restrict__ out_hidden) {
    int tid = threadIdx.x;
    int w = tid >> 5;
    int lane = tid & 31;
    int s = lane & 15;

    int d = blockIdx.x * 8 + w;
    int tA = (d >> 2) * 2;
    int tB = tA + 1;
    int c = 2 * (d & 3) + (lane >> 4);

    float h0v = g_H0[c * 16 + s];
    float hA = h0v, hB = h0v;

    #pragma unroll
    for (int k = 0; k < 11; k++) {
        int bA = (tA >> k) & 1;
        int bB = (tB >> k) & 1;
        if (bA | bB) {
            const float* P = g_pow + (k * 8 + c) * 256;
            float pcol[16];
            #pragma unroll
            for (int i = 0; i < 16; i++) pcol[i] = P[i * 16 + s];
            if (bA) {
                float n0 = 0.f, n1 = 0.f;
                #pragma unroll
                for (int i = 0; i < 8; i++) {
                    n0 = fmaf(__shfl_sync(0xffffffffu, hA, 2 * i,     16), pcol[2 * i],     n0);
                    n1 = fmaf(__shfl_sync(0xffffffffu, hA, 2 * i + 1, 16), pcol[2 * i + 1], n1);
                }
                hA = n0 + n1;
            }
            if (bB) {
                float n0 = 0.f, n1 = 0.f;
                #pragma unroll
                for (int i = 0; i < 8; i++) {
                    n0 = fmaf(__shfl_sync(0xffffffffu, hB, 2 * i,     16), pcol[2 * i],     n0);
                    n1 = fmaf(__shfl_sync(0xffffffffu, hB, 2 * i + 1, 16), pcol[2 * i + 1], n1);
                }
                hB = n0 + n1;
            }
        }
    }
    int idxA = (tA * 8 + c) * 16 + s;
    int idxB = (tB * 8 + c) * 16 + s;
    g_H[idxA] = hA;
    g_H[idxB] = hB;
    if (out_hidden) { out_hidden[idxA] = __logf(hA); out_hidden[idxB] = __logf(hB); }
}

// dummy to align ncu capture (absolute launch index 3 = k_main)
__global__ void k_nop() {}

// ---------------- k_main: 128n x 64t, warp-uniform tg, stg.cs + stationary fast path ----------------
__global__ void __launch_bounds__(256, 2)
k_main(float* __restrict__ out_obs, float* __restrict__ out_obs_c) {
    extern __shared__ float smem[];
    float* Es  = smem;                    // [128 rows][128 n] = 16384 f (64KB)
    float* Hs  = smem + 16384;            // [64 t][128]       = 8192 f (32KB)
    float* CWs = smem + 16384 + 8192;     // [64 t][8 c]       = 512 f (2KB)
    __shared__ int sflag;
    int tid = threadIdx.x;
    int n0 = blockIdx.x * NT;
    int t0 = blockIdx.y * TT;

    if (tid == 0) sflag = 0;

    // E tile (zero-fill OOB n): 128 rows x 128 n
    float4* Es4 = (float4*)Es;
    for (int idx = tid; idx < 128 * 32; idx += 256) {
        int r = idx >> 5, q = idx & 31;
        int n = n0 + q * 4;
        float4 v = make_float4(0.f, 0.f, 0.f, 0.f);
        if (n < N_DIM) v = *(const float4*)(g_E + (size_t)r * N_DIM + n);
        Es4[idx] = v;
    }
    // H tile
    {
        const float4* src = (const float4*)(g_H + t0 * 128);
        float4* dst = (float4*)Hs;
        for (int idx = tid; idx < 2048; idx += 256) dst[idx] = src[idx];
    }
    for (int idx = tid; idx < 512; idx += 256) CWs[idx] = g_cw[t0 * 8 + idx];
    __syncthreads();

    // convergence check: is H constant across the 64-t tile?
    {
        float diff = 0.f;
        for (int idx = tid; idx < TT * 128; idx += 256)
            diff = fmaxf(diff, fabsf(Hs[idx] - Hs[idx & 127]));
        if (diff > 2e-7f) sflag = 1;
    }
    __syncthreads();
    int converged = (sflag == 0);

    int nq = tid & 31;        // n-quad (warp-varying)
    int tg = tid >> 5;        // warp id = t-group (8 t each, warp-uniform)
    int tl0 = tg * 8;
    int nvalid = (n0 + nq * 4) < N_DIM;

    u64 wsum[8][2];
    #pragma unroll
    for (int a = 0; a < 8; a++) { wsum[a][0] = 0ULL; wsum[a][1] = 0ULL; }

    const ulonglong2* Es2 = (const ulonglong2*)Es;  // row = 128 floats = 32 ulonglong2

    if (converged) {
        // ---------- FAST PATH: H identical across tile; dot + log once per c ----------
        #pragma unroll 1
        for (int c = 0; c < 8; c++) {
            u64 acc0 = 0ULL, acc1 = 0ULL;
            #pragma unroll
            for (int sq = 0; sq < 4; sq++) {
                float4 hv = *(const float4*)(Hs + c * 16 + sq * 4);  // row 0, warp-broadcast
                #pragma unroll
                for (int si = 0; si < 4; si++) {
                    ulonglong2 ev = Es2[(c * 16 + sq * 4 + si) * 32 + nq];
                    float hsc = ((const float*)&hv)[si];
                    u64 hh = pack2(hsc, hsc);
                    acc0 = fma2(hh, ev.x, acc0);
                    acc1 = fma2(hh, ev.y, acc1);
                }
            }
            float2 q0 = unpack2(acc0), q1 = unpack2(acc1);
            float4 lo = make_float4(__logf(q0.x), __logf(q0.y), __logf(q1.x), __logf(q1.y));
            #pragma unroll
            for (int tt = 0; tt < 8; tt++) {
                float cw = CWs[(tl0 + tt) * 8 + c];
                u64 cwp = pack2(cw, cw);
                wsum[tt][0] = fma2(cwp, acc0, wsum[tt][0]);
                wsum[tt][1] = fma2(cwp, acc1, wsum[tt][1]);
                if (out_obs_c && nvalid) {
                    int t = t0 + tl0 + tt;
                    stg_cs(out_obs_c + (size_t)(t * 8 + c) * N_DIM + n0 + nq * 4, lo);
                }
            }
        }
    } else {
        // ---------- SLOW PATH: exact per-t (R11) ----------
        #pragma unroll 1
        for (int c = 0; c < 8; c++) {
            u64 acc[8][2];
            #pragma unroll
            for (int a = 0; a < 8; a++) { acc[a][0] = 0ULL; acc[a][1] = 0ULL; }
            #pragma unroll
            for (int sq = 0; sq < 4; sq++) {
                ulonglong2 ev[4];
                #pragma unroll
                for (int si = 0; si < 4; si++)
                    ev[si] = Es2[(c * 16 + sq * 4 + si) * 32 + nq];
                #pragma unroll
                for (int tt = 0; tt < 8; tt++) {
                    float4 hv = *(const float4*)(Hs + (tl0 + tt) * 128 + c * 16 + sq * 4);
                    #pragma unroll
                    for (int si = 0; si < 4; si++) {
                        float hsc = ((const float*)&hv)[si];
                        u64 hh = pack2(hsc, hsc);
                        acc[tt][0] = fma2(hh, ev[si].x, acc[tt][0]);
                        acc[tt][1] = fma2(hh, ev[si].y, acc[tt][1]);
                    }
                }
            }
            #pragma unroll
            for (int tt = 0; tt < 8; tt++) {
                float cw = CWs[(tl0 + tt) * 8 + c];
                u64 cwp = pack2(cw, cw);
                wsum[tt][0] = fma2(cwp, acc[tt][0], wsum[tt][0]);
                wsum[tt][1] = fma2(cwp, acc[tt][1], wsum[tt][1]);
                if (out_obs_c && nvalid) {
                    float2 p0 = unpack2(acc[tt][0]);
                    float2 p1 = unpack2(acc[tt][1]);
                    float4 o = make_float4(__logf(p0.x), __logf(p0.y), __logf(p1.x), __logf(p1.y));
                    int t = t0 + tl0 + tt;
                    stg_cs(out_obs_c + (size_t)(t * 8 + c) * N_DIM + n0 + nq * 4, o);
                }
            }
        }
    }

    // store log_obs (both paths)
    #pragma unroll
    for (int tt = 0; tt < 8; tt++) {
        if (nvalid) {
            float2 p0 = unpack2(wsum[tt][0]);
            float2 p1 = unpack2(wsum[tt][1]);
            float4 o = make_float4(__logf(p0.x), __logf(p0.y), __logf(p1.x), __logf(p1.y));
            int t = t0 + tl0 + tt;
            stg_cs(out_obs + (size_t)t * N_DIM + n0 + nq * 4, o);
        }
    }
}

// ---------------- launch ----------------
extern "C" void kernel_launch(void* const* d_in, const int* in_sizes, int n_in,
                              void* d_out, int out_size) {
    const float* cw_logits   = (const float*)d_in[0];  // (T, C)
    const float* init_logits = (const float*)d_in[1];  // (C, S)
    const float* em_logits   = (const float*)d_in[2];  // (C, S, N)
    const float* tr_logits   = (const float*)d_in[3];  // (C, S, S)
    float* out = (float*)d_out;

    const long long s0 = (long long)T_DIM * N_DIM;
    const long long s1 = (long long)T_DIM * C_DIM * N_DIM;
    const long long s2 = (long long)T_DIM * C_DIM * S_DIM;
    long long osz = (long long)out_size;

    float* out_obs    = out;
    float* out_obs_c  = (osz >= s0 + s1)      ? out + s0      : nullptr;
    float* out_hidden = (osz >= s0 + s1 + s2) ? out + s0 + s1 : nullptr;

    const int prep_smem = POW_FLOATS * 4;              // 90112
    const int main_smem = (16384 + 8192 + 512) * 4;    // 100352
    cudaFuncSetAttribute(k_prep, cudaFuncAttributeMaxDynamicSharedMemorySize, prep_smem);
    cudaFuncSetAttribute(k_main, cudaFuncAttributeMaxDynamicSharedMemorySize, main_smem);

    k_prep<<<9 + C_DIM * S_DIM, 256, prep_smem>>>(init_logits, tr_logits, cw_logits, em_logits);
    k_H<<<512, 256>>>(out_hidden);
    k_nop<<<1, 32>>>();   // aligns ncu capture (index 3) onto k_main

    dim3 grid((N_DIM + NT - 1) / NT, T_DIM / TT);
    k_main<<<grid, 256, main_smem>>>(out_obs, out_obs_c);
}